// round 1
// baseline (speedup 1.0000x reference)
#include <cuda_runtime.h>
#include <cuda_bf16.h>

#define H  100000
#define E  200000
#define NI 1000000
#define DH 128
#define DE 64
#define DO 128

// ---------------- scratch (device globals: no allocations allowed) ----------
__device__ float4 g_edge_acc[E * 32];   // [E][128] as float4
__device__ float  g_edge_cnt[E];
__device__ float4 g_edge_msg[E * 32];   // [E][128]
__device__ float4 g_node_acc[H * 32];   // [H][128]
__device__ float  g_node_cnt[H];

// transposed weights: [k][out] so the k-loop load is lane-coalesced float4
__device__ float4 g_W1t[192 * 32];      // from We1 [128][192]
__device__ float4 g_W2t[128 * 32];      // from We2 [128][128]
__device__ float4 g_Wpt[128 * 32];      // from Wp
__device__ float4 g_Wn1t[128 * 32];
__device__ float4 g_Wn2t[128 * 32];

// ---------------- zero accumulators -----------------------------------------
__global__ void k_zero() {
    int i = blockIdx.x * blockDim.x + threadIdx.x;
    float4 z = make_float4(0.f, 0.f, 0.f, 0.f);
    if (i < E * 32) g_edge_acc[i] = z;
    if (i < H * 32) g_node_acc[i] = z;
    if (i < E) g_edge_cnt[i] = 0.f;
    if (i < H) g_node_cnt[i] = 0.f;
}

// ---------------- transpose weights -----------------------------------------
__global__ void k_prep(const float* __restrict__ We1, const float* __restrict__ We2,
                       const float* __restrict__ Wp,  const float* __restrict__ Wn1,
                       const float* __restrict__ Wn2) {
    int i = blockIdx.x * blockDim.x + threadIdx.x;
    if (i < 192 * 128) {
        int k = i / 128, o = i % 128;
        ((float*)g_W1t)[i] = We1[o * 192 + k];
    }
    if (i < 128 * 128) {
        int k = i / 128, o = i % 128;
        ((float*)g_W2t)[i]  = We2[o * 128 + k];
        ((float*)g_Wpt)[i]  = Wp [o * 128 + k];
        ((float*)g_Wn1t)[i] = Wn1[o * 128 + k];
        ((float*)g_Wn2t)[i] = Wn2[o * 128 + k];
    }
}

// ---------------- vectorized global reduction helper ------------------------
__device__ __forceinline__ void red_add_v4(float* p, float4 v) {
    unsigned long long a = (unsigned long long)__cvta_generic_to_global(p);
    asm volatile("red.global.add.v4.f32 [%0], {%1, %2, %3, %4};"
                 :: "l"(a), "f"(v.x), "f"(v.y), "f"(v.z), "f"(v.w) : "memory");
}

// ---------------- scatter node -> edge ---------------------------------------
// one warp per incidence; lane c handles floats [4c, 4c+4)
__global__ void k_scat_ne(const float4* __restrict__ xh,
                          const int* __restrict__ fg, const int* __restrict__ res) {
    int t = blockIdx.x * blockDim.x + threadIdx.x;   // < NI*32 = 32M
    int i = t >> 5, c = t & 31;
    int f = fg[i], r = res[i];
    float4 v = xh[f * 32 + c];
    red_add_v4((float*)&g_edge_acc[r * 32 + c], v);
    if (c == 0) atomicAdd(&g_edge_cnt[r], 1.f);
}

// ---------------- scatter edge -> node ---------------------------------------
__global__ void k_scat_en(const int* __restrict__ fg, const int* __restrict__ res) {
    int t = blockIdx.x * blockDim.x + threadIdx.x;
    int i = t >> 5, c = t & 31;
    int f = fg[i], r = res[i];
    float4 v = g_edge_msg[r * 32 + c];
    red_add_v4((float*)&g_node_acc[f * 32 + c], v);
    if (c == 0) atomicAdd(&g_node_cnt[f], 1.f);
}

// ---------------- edge MLP ---------------------------------------------------
// 256 thr = 8 warps / block. Each warp: 4 edges, lane owns out-dims [4l,4l+4).
// Per k-step: 1 LDG.128 (weights) + 4 broadcast LDS + 16 FMA.
__global__ void __launch_bounds__(256) k_edge_mlp(const float4* __restrict__ attr,
                                                  const float* __restrict__ be1,
                                                  const float* __restrict__ be2) {
    __shared__ float s_ein[8][4][192];
    __shared__ float s_h[8][4][128];
    int warp = threadIdx.x >> 5, lane = threadIdx.x & 31;
    int e0 = (blockIdx.x * 8 + warp) * 4;            // E divisible by 4*8*6250

    // stage inputs: mean of members + edge attr
    #pragma unroll
    for (int j = 0; j < 4; j++) {
        int e = e0 + j;
        float inv = 1.f / fmaxf(g_edge_cnt[e], 1.f);
        float4 a = g_edge_acc[e * 32 + lane];
        ((float4*)&s_ein[warp][j][0])[lane] = make_float4(a.x*inv, a.y*inv, a.z*inv, a.w*inv);
        if (lane < 16)
            ((float4*)&s_ein[warp][j][128])[lane] = attr[e * 16 + lane];
    }
    __syncwarp();

    // GEMM1: [4 x 192] @ [192 x 128] + bias, relu
    float4 acc[4];
    float4 b1 = ((const float4*)be1)[lane];
    #pragma unroll
    for (int j = 0; j < 4; j++) acc[j] = b1;
    #pragma unroll 4
    for (int k = 0; k < 192; k++) {
        float4 w = g_W1t[k * 32 + lane];
        #pragma unroll
        for (int j = 0; j < 4; j++) {
            float s = s_ein[warp][j][k];
            acc[j].x += w.x * s; acc[j].y += w.y * s;
            acc[j].z += w.z * s; acc[j].w += w.w * s;
        }
    }
    #pragma unroll
    for (int j = 0; j < 4; j++) {
        float4 r = make_float4(fmaxf(acc[j].x, 0.f), fmaxf(acc[j].y, 0.f),
                               fmaxf(acc[j].z, 0.f), fmaxf(acc[j].w, 0.f));
        ((float4*)&s_h[warp][j][0])[lane] = r;
    }
    __syncwarp();

    // GEMM2: [4 x 128] @ [128 x 128] + bias
    float4 b2 = ((const float4*)be2)[lane];
    #pragma unroll
    for (int j = 0; j < 4; j++) acc[j] = b2;
    #pragma unroll 4
    for (int k = 0; k < 128; k++) {
        float4 w = g_W2t[k * 32 + lane];
        #pragma unroll
        for (int j = 0; j < 4; j++) {
            float s = s_h[warp][j][k];
            acc[j].x += w.x * s; acc[j].y += w.y * s;
            acc[j].z += w.z * s; acc[j].w += w.w * s;
        }
    }
    #pragma unroll
    for (int j = 0; j < 4; j++)
        g_edge_msg[(e0 + j) * 32 + lane] = acc[j];
}

// ---------------- node MLP + residual + relu + layernorm ---------------------
__global__ void __launch_bounds__(256) k_node(const float4* __restrict__ xh,
                                              const float* __restrict__ bp,
                                              const float* __restrict__ bn1,
                                              const float* __restrict__ bn2,
                                              const float4* __restrict__ gamma4,
                                              const float4* __restrict__ beta4,
                                              float4* __restrict__ out) {
    __shared__ float s_buf[8][4][128];
    int warp = threadIdx.x >> 5, lane = threadIdx.x & 31;
    int n0 = (blockIdx.x * 8 + warp) * 4;            // H divisible by 4*8*3125

    // --- p = Wp @ x + bp  (stage x rows) ---
    #pragma unroll
    for (int j = 0; j < 4; j++)
        ((float4*)&s_buf[warp][j][0])[lane] = xh[(n0 + j) * 32 + lane];
    __syncwarp();

    float4 p[4];
    float4 bpv = ((const float4*)bp)[lane];
    #pragma unroll
    for (int j = 0; j < 4; j++) p[j] = bpv;
    #pragma unroll 4
    for (int k = 0; k < 128; k++) {
        float4 w = g_Wpt[k * 32 + lane];
        #pragma unroll
        for (int j = 0; j < 4; j++) {
            float s = s_buf[warp][j][k];
            p[j].x += w.x * s; p[j].y += w.y * s;
            p[j].z += w.z * s; p[j].w += w.w * s;
        }
    }
    __syncwarp();

    // --- stage node_msg = node_acc / cnt ---
    #pragma unroll
    for (int j = 0; j < 4; j++) {
        int n = n0 + j;
        float inv = 1.f / fmaxf(g_node_cnt[n], 1.f);
        float4 a = g_node_acc[n * 32 + lane];
        ((float4*)&s_buf[warp][j][0])[lane] = make_float4(a.x*inv, a.y*inv, a.z*inv, a.w*inv);
    }
    __syncwarp();

    // --- t = relu(Wn1 @ m + bn1) ---
    float4 acc[4];
    float4 b1 = ((const float4*)bn1)[lane];
    #pragma unroll
    for (int j = 0; j < 4; j++) acc[j] = b1;
    #pragma unroll 4
    for (int k = 0; k < 128; k++) {
        float4 w = g_Wn1t[k * 32 + lane];
        #pragma unroll
        for (int j = 0; j < 4; j++) {
            float s = s_buf[warp][j][k];
            acc[j].x += w.x * s; acc[j].y += w.y * s;
            acc[j].z += w.z * s; acc[j].w += w.w * s;
        }
    }
    __syncwarp();
    #pragma unroll
    for (int j = 0; j < 4; j++)
        ((float4*)&s_buf[warp][j][0])[lane] =
            make_float4(fmaxf(acc[j].x, 0.f), fmaxf(acc[j].y, 0.f),
                        fmaxf(acc[j].z, 0.f), fmaxf(acc[j].w, 0.f));
    __syncwarp();

    // --- u = Wn2 @ t + bn2 ; z = relu(p + u) ; layernorm ---
    float4 b2 = ((const float4*)bn2)[lane];
    #pragma unroll
    for (int j = 0; j < 4; j++) acc[j] = b2;
    #pragma unroll 4
    for (int k = 0; k < 128; k++) {
        float4 w = g_Wn2t[k * 32 + lane];
        #pragma unroll
        for (int j = 0; j < 4; j++) {
            float s = s_buf[warp][j][k];
            acc[j].x += w.x * s; acc[j].y += w.y * s;
            acc[j].z += w.z * s; acc[j].w += w.w * s;
        }
    }

    float4 g = gamma4[lane], b = beta4[lane];
    #pragma unroll
    for (int j = 0; j < 4; j++) {
        float4 z = make_float4(fmaxf(p[j].x + acc[j].x, 0.f),
                               fmaxf(p[j].y + acc[j].y, 0.f),
                               fmaxf(p[j].z + acc[j].z, 0.f),
                               fmaxf(p[j].w + acc[j].w, 0.f));
        float s  = z.x + z.y + z.z + z.w;
        float q  = z.x*z.x + z.y*z.y + z.z*z.z + z.w*z.w;
        #pragma unroll
        for (int o = 16; o > 0; o >>= 1) {
            s += __shfl_xor_sync(0xFFFFFFFFu, s, o);
            q += __shfl_xor_sync(0xFFFFFFFFu, q, o);
        }
        float mu  = s * (1.f / 128.f);
        float var = q * (1.f / 128.f) - mu * mu;
        float r   = rsqrtf(var + 1e-5f);
        out[(n0 + j) * 32 + lane] =
            make_float4((z.x - mu) * r * g.x + b.x, (z.y - mu) * r * g.y + b.y,
                        (z.z - mu) * r * g.z + b.z, (z.w - mu) * r * g.w + b.w);
    }
}

// ---------------- launch -----------------------------------------------------
extern "C" void kernel_launch(void* const* d_in, const int* in_sizes, int n_in,
                              void* d_out, int out_size) {
    const float* x_h   = (const float*)d_in[0];
    const float* attr  = (const float*)d_in[1];
    const float* Wp    = (const float*)d_in[2];
    const float* bp    = (const float*)d_in[3];
    const float* We1   = (const float*)d_in[4];
    const float* be1   = (const float*)d_in[5];
    const float* We2   = (const float*)d_in[6];
    const float* be2   = (const float*)d_in[7];
    const float* Wn1   = (const float*)d_in[8];
    const float* bn1   = (const float*)d_in[9];
    const float* Wn2   = (const float*)d_in[10];
    const float* bn2   = (const float*)d_in[11];
    const float* gamma = (const float*)d_in[12];
    const float* beta  = (const float*)d_in[13];
    const int*   fg    = (const int*)d_in[14];
    const int*   res   = (const int*)d_in[15];

    k_zero<<<25000, 256>>>();                                   // E*32 = 6.4M
    k_prep<<<96, 256>>>(We1, We2, Wp, Wn1, Wn2);                // 24576 threads
    k_scat_ne<<<125000, 256>>>((const float4*)x_h, fg, res);    // NI*32 = 32M
    k_edge_mlp<<<6250, 256>>>((const float4*)attr, be1, be2);   // E/32 warps*4
    k_scat_en<<<125000, 256>>>(fg, res);
    k_node<<<3125, 256>>>((const float4*)x_h, bp, bn1, bn2,
                          (const float4*)gamma, (const float4*)beta,
                          (float4*)d_out);
}